// round 7
// baseline (speedup 1.0000x reference)
#include <cuda_runtime.h>
#include <stdint.h>

// MeanField on GB300 — persistent single-kernel version.
// 144 CTAs (1/SM, guaranteed co-resident: smem-limited occupancy 1, 144 <= 148 SMs),
// 256 threads each; CTA c owns pixels [c*4096, (c+1)*4096) (36 CTAs per batch,
// no CTA straddles a batch). Pairwise weights (9 floats/px, 144 KB/CTA) are
// computed directly into dynamic shared memory and reused across all 20
// mean-field iterations. Binary state (2 bits/px, 1 byte stored) ping-pongs in
// global memory; iterations are separated by a software grid barrier.

#define KW   384
#define KH   384
#define KHW  (KW * KH)              // 147456
#define KB   4
#define NPIX (KB * KHW)             // 589824
#define ITERS 20

#define NCTA 144
#define NTH  256
#define QUADS_PER_CTA 1024          // 4096 px per CTA
#define QUADS_PER_TH  4
#define CTAS_PER_BATCH 36
#define SMEM_BYTES (9 * QUADS_PER_CTA * 16)   // 147456 B

#define MPAD 512                    // mask pad covers +-388 byte reach

static __device__ __align__(16) unsigned char g_mA_raw[NPIX + 2 * MPAD];
static __device__ __align__(16) unsigned char g_mB_raw[NPIX + 2 * MPAD];
static __device__ int g_cnt[KB];
static __device__ int g_bar_count;  // zero-init; returns to 0 after each barrier
static __device__ int g_bar_gen;    // zero-init; monotone across graph replays

// Grid-wide barrier. Generation-based: no state reset needed between launches
// or graph replays (gen only ever increments; count always drains to 0).
// Safe because all NCTA CTAs are co-resident (occupancy 1 CTA/SM by smem).
__device__ __forceinline__ void grid_barrier() {
    __syncthreads();
    if (threadIdx.x == 0) {
        int gen = *(volatile int*)&g_bar_gen;    // read BEFORE arriving
        __threadfence();                          // publish this CTA's writes
        if (atomicAdd(&g_bar_count, 1) == NCTA - 1) {
            atomicExch(&g_bar_count, 0);          // drain for next episode
            __threadfence();
            atomicAdd(&g_bar_gen, 1);             // release
        } else {
            while (*(volatile int*)&g_bar_gen == gen) { }
            __threadfence();                      // acquire
        }
    }
    __syncthreads();
}

__device__ __forceinline__ unsigned byte_at(const uint32_t W[3], int t) {
    // t in [-1, 4]; fully constant-folded under #pragma unroll
    if (t < 0)  return (W[0] >> 24) & 0xffu;
    if (t < 4)  return (W[1] >> (8 * t)) & 0xffu;
    return W[2] & 0xffu;
}

__global__ void __launch_bounds__(NTH) mf_persistent_kernel(
    const float* __restrict__ x,
    const float* __restrict__ tgt,
    const float* __restrict__ fm,
    float* __restrict__ out)
{
    extern __shared__ float4 wq4[];   // [9][QUADS_PER_CTA] weight quads
    const int cta  = blockIdx.x;
    const int tid  = threadIdx.x;
    const int qbase = cta * QUADS_PER_CTA;
    const int b    = cta / CTAS_PER_BATCH;        // batch of this CTA

    if (cta == 0 && tid < KB) g_cnt[tid] = 0;     // pre-barrier; atomics are post

    const float* f0 = fm + (size_t)(b * 3 + 0) * KHW;
    const float* f1 = fm + (size_t)(b * 3 + 1) * KHW;
    const float* f2 = fm + (size_t)(b * 3 + 2) * KHW;

    // ================= phase 1: weights -> smem, init state -> g_mA ========
    // Weight (bit-faithful to reference): w = 3*exp(-2*sum_c d_c^2 - SP_k),
    // zero padding applied AFTER fm+10 -> OOB gives exp(~-600) == +0.0f
    // exactly, which licenses the branch-free iteration below.
    // Init: xm = x*t > 0.5 -> ch1=0.55 else 0.45, ch0 = 1-ch1 (exact in fp32).
    {
        const float sp1 = 1.0f / 1800.0f;
        const float sp2 = 2.0f / 1800.0f;
        const float SP[9] = { sp2, sp1, sp2,  sp1, 0.f, sp1,  sp2, sp1, sp2 };

#pragma unroll 1
        for (int ph = 0; ph < QUADS_PER_TH; ph++) {
            int lq = ph * NTH + tid;          // 0..1023
            int g0 = (qbase + lq) * 4;        // global pixel (row-aligned quad)
            int p  = g0 - b * KHW;            // batch-local pixel
            int y  = p / KW, xc = p - y * KW;

            // ---- init mask word ----
            float4 xv = *(const float4*)(x + g0);
            float4 tv = *(const float4*)(tgt + g0);
            float xs[4] = { xv.x, xv.y, xv.z, xv.w };
            float ts[4] = { tv.x, tv.y, tv.z, tv.w };
            uint32_t mw = 0;
#pragma unroll
            for (int j = 0; j < 4; j++) {
                unsigned m1 = (__fmul_rn(xs[j], ts[j]) > 0.5f) ? 1u : 0u;
                mw |= (m1 | ((m1 ^ 1u) << 1)) << (8 * j);
            }
            *(uint32_t*)(g_mA_raw + MPAD + g0) = mw;

            // ---- center values for the 4 pixels ----
            float c0[4], c1[4], c2[4];
#pragma unroll
            for (int j = 0; j < 4; j++) {
                c0[j] = __fadd_rn(f0[p + j], 10.0f);
                c1[j] = __fadd_rn(f1[p + j], 10.0f);
                c2[j] = __fadd_rn(f2[p + j], 10.0f);
            }

            // ---- 9 weights x 4 pixels ----
#pragma unroll
            for (int k = 0; k < 9; k++) {
                int ny = y + k / 3 - 1;
                int kx = k % 3 - 1;
                float wv[4];
#pragma unroll
                for (int j = 0; j < 4; j++) {
                    int nx = xc + j + kx;
                    float n0 = 0.0f, n1 = 0.0f, n2 = 0.0f;  // pad AFTER +10
                    if (ny >= 0 && ny < KH && nx >= 0 && nx < KW) {
                        int q = ny * KW + nx;
                        n0 = __fadd_rn(f0[q], 10.0f);
                        n1 = __fadd_rn(f1[q], 10.0f);
                        n2 = __fadd_rn(f2[q], 10.0f);
                    }
                    float d0 = __fsub_rn(n0, c0[j]);
                    float d1 = __fsub_rn(n1, c1[j]);
                    float d2 = __fsub_rn(n2, c2[j]);
                    float ss = __fadd_rn(__fadd_rn(__fmul_rn(d0, d0),
                                                   __fmul_rn(d1, d1)),
                                         __fmul_rn(d2, d2));
                    float color = __fmul_rn(ss, -2.0f);   // exact: -ss/0.5
                    float arg   = __fsub_rn(color, SP[k]);
                    wv[j] = __fmul_rn(3.0f, expf(arg));
                }
                wq4[k * QUADS_PER_CTA + lq] =
                    make_float4(wv[0], wv[1], wv[2], wv[3]);
            }
        }
    }
    grid_barrier();   // init masks + (local) weights ready

    // ================= phase 2: 20 mean-field iterations ===================
    // Per pixel (bit-faithful): a{0,1} = sum_k w_k * (-log r_k) in k order
    // (separate rn mul/add); f0=exp(-a0); f1=exp(-a1)*t; +1e-6; two IEEE
    // divisions; two independent >0.5 thresholds. OOB neighbors: w == +0.0f
    // exactly, u is finite -> contribution +0.0f regardless of pad bytes.
    const float L45 = -logf(0.45f);
    const float L55 = -logf(0.55f);

#pragma unroll 1
    for (int it = 0; it < ITERS; it++) {
        const unsigned char* __restrict__ mIn  =
            ((it & 1) ? g_mB_raw : g_mA_raw) + MPAD;
        unsigned char* __restrict__ mOut =
            ((it & 1) ? g_mA_raw : g_mB_raw) + MPAD;

#pragma unroll 1
        for (int ph = 0; ph < QUADS_PER_TH; ph++) {
            int lq = ph * NTH + tid;
            int g0 = (qbase + lq) * 4;

            // front-batched gmem loads: 9 mask words + tgt quad
            uint32_t Wm[3][3];
#pragma unroll
            for (int r = 0; r < 3; r++) {
                const unsigned char* row = mIn + g0 + (r - 1) * KW;
                Wm[r][0] = *(const uint32_t*)(row - 4);
                Wm[r][1] = *(const uint32_t*)(row);
                Wm[r][2] = *(const uint32_t*)(row + 4);
            }
            float4 tv = *(const float4*)(tgt + g0);

            // weights from smem
            float4 wk[9];
#pragma unroll
            for (int k = 0; k < 9; k++)
                wk[k] = wq4[k * QUADS_PER_CTA + lq];

            // u windows (each slot shared by up to 3 of the 4 pixels)
            float u0v[3][6], u1v[3][6];
#pragma unroll
            for (int r = 0; r < 3; r++) {
#pragma unroll
                for (int t = -1; t <= 4; t++) {
                    unsigned m = byte_at(Wm[r], t);
                    u0v[r][t + 1] = (m & 2u) ? L55 : L45;
                    u1v[r][t + 1] = (m & 1u) ? L55 : L45;
                }
            }

            float a0[4] = {0.f, 0.f, 0.f, 0.f};
            float a1[4] = {0.f, 0.f, 0.f, 0.f};
#pragma unroll
            for (int r = 0; r < 3; r++) {
#pragma unroll
                for (int c = 0; c < 3; c++) {
                    int k = r * 3 + c;
                    float ws[4] = { wk[k].x, wk[k].y, wk[k].z, wk[k].w };
#pragma unroll
                    for (int j = 0; j < 4; j++) {
                        a0[j] = __fadd_rn(a0[j], __fmul_rn(ws[j], u0v[r][j + c]));
                        a1[j] = __fadd_rn(a1[j], __fmul_rn(ws[j], u1v[r][j + c]));
                    }
                }
            }

            float ts[4] = { tv.x, tv.y, tv.z, tv.w };
            uint32_t outw = 0;
#pragma unroll
            for (int j = 0; j < 4; j++) {
                float f0e = expf(-a0[j]);
                float f1e = __fmul_rn(expf(-a1[j]), ts[j]);
                f0e = __fadd_rn(f0e, 1e-6f);
                f1e = __fadd_rn(f1e, 1e-6f);
                float s = __fadd_rn(f0e, f1e);
                unsigned nm = 0;
                if (__fdiv_rn(f1e, s) > 0.5f) nm |= 1u;
                if (__fdiv_rn(f0e, s) > 0.5f) nm |= 2u;
                outw |= nm << (8 * j);
            }
            *(uint32_t*)(mOut + g0) = outw;
        }
        grid_barrier();   // also publishes mOut for neighbor CTAs
    }
    // ITERS even -> final state in g_mA

    // ================= phase 3: output + validity ==========================
    int cnt = 0;
#pragma unroll 1
    for (int ph = 0; ph < QUADS_PER_TH; ph++) {
        int lq = ph * NTH + tid;
        int g0 = (qbase + lq) * 4;
        uint32_t w = *(const uint32_t*)(g_mA_raw + MPAD + g0);
        float4 ov;
        ov.x = (float)( w        & 1u);
        ov.y = (float)((w >> 8)  & 1u);
        ov.z = (float)((w >> 16) & 1u);
        ov.w = (float)((w >> 24) & 1u);
        *(float4*)(out + g0) = ov;
        cnt += __popc(w & 0x01010101u);
    }
#pragma unroll
    for (int d = 16; d > 0; d >>= 1)
        cnt += __shfl_down_sync(0xffffffffu, cnt, d);
    if ((tid & 31) == 0) atomicAdd(&g_cnt[b], cnt);

    grid_barrier();       // all counts in

    // valid = (count >= HW*0.05=7372.8) && (count <= HW*0.95=140083.2);
    // count is an exact integer -> >=7373 && <=140083.
    if (cta == 0 && tid < KB) {
        int c = g_cnt[tid];
        out[NPIX + tid] = (c >= 7373 && c <= 140083) ? 1.0f : 0.0f;
    }
}

extern "C" void kernel_launch(void* const* d_in, const int* in_sizes, int n_in,
                              void* d_out, int out_size) {
    (void)in_sizes; (void)n_in; (void)out_size;
    const float* x   = (const float*)d_in[0];   // [4,1,384,384]
    const float* tgt = (const float*)d_in[1];   // [4,1,384,384]
    const float* fm  = (const float*)d_in[2];   // [4,3,384,384]
    float* out = (float*)d_out;                 // [4*384*384 mask] ++ [4 valid]

    // 147456 B dynamic smem > 48 KB default: opt in every call (idempotent,
    // not a stream op -> graph-capture safe).
    cudaFuncSetAttribute(mf_persistent_kernel,
                         cudaFuncAttributeMaxDynamicSharedMemorySize,
                         SMEM_BYTES);
    mf_persistent_kernel<<<NCTA, NTH, SMEM_BYTES>>>(x, tgt, fm, out);
}

// round 8
// speedup vs baseline: 1.2022x; 1.2022x over previous
#include <cuda_runtime.h>
#include <stdint.h>

// MeanField on GB300 — persistent single-kernel, high-occupancy version.
// 144 CTAs x 1024 threads (1 CTA/SM by smem, 32 warps/SM; 144 <= 148 SMs so
// all CTAs are co-resident and the software grid barrier is safe).
// CTA c owns pixels [c*4096, (c+1)*4096); thread t owns quad t (one 4-pixel
// row-aligned quad). Pairwise weights (9 floats/px, 144 KB/CTA) are computed
// directly into dynamic shared memory and reused across all 20 iterations.
// Binary state (2 bits/px, 1 byte stored) ping-pongs in global memory.

#define KW   384
#define KH   384
#define KHW  (KW * KH)              // 147456
#define KB   4
#define NPIX (KB * KHW)             // 589824
#define ITERS 20

#define NCTA 144
#define NTH  1024
#define QUADS_PER_CTA 1024          // 4096 px per CTA; == NTH (1 quad/thread)
#define CTAS_PER_BATCH 36
#define SMEM_BYTES (9 * QUADS_PER_CTA * 16)   // 147456 B

#define MPAD 512                    // mask pad covers +-388 byte reach

static __device__ __align__(16) unsigned char g_mA_raw[NPIX + 2 * MPAD];
static __device__ __align__(16) unsigned char g_mB_raw[NPIX + 2 * MPAD];
static __device__ int g_cnt[KB];
static __device__ int g_bar_count;  // zero-init; returns to 0 after each barrier
static __device__ int g_bar_gen;    // zero-init; monotone across graph replays

// Grid-wide barrier. Generation-based: no state reset needed between launches
// or graph replays (gen only ever increments; count always drains to 0).
// Safe because all NCTA CTAs are co-resident (occupancy 1 CTA/SM by smem).
__device__ __forceinline__ void grid_barrier() {
    __syncthreads();
    if (threadIdx.x == 0) {
        int gen = *(volatile int*)&g_bar_gen;    // read BEFORE arriving
        __threadfence();                          // publish this CTA's writes
        if (atomicAdd(&g_bar_count, 1) == NCTA - 1) {
            atomicExch(&g_bar_count, 0);          // drain for next episode
            __threadfence();
            atomicAdd(&g_bar_gen, 1);             // release
        } else {
            while (*(volatile int*)&g_bar_gen == gen) { }
            __threadfence();                      // acquire
        }
    }
    __syncthreads();
}

__device__ __forceinline__ unsigned byte_at(const uint32_t W[3], int t) {
    // t in [-1, 4]; fully constant-folded under #pragma unroll
    if (t < 0)  return (W[0] >> 24) & 0xffu;
    if (t < 4)  return (W[1] >> (8 * t)) & 0xffu;
    return W[2] & 0xffu;
}

__global__ void __launch_bounds__(NTH, 1) mf_persistent_kernel(
    const float* __restrict__ x,
    const float* __restrict__ tgt,
    const float* __restrict__ fm,
    float* __restrict__ out)
{
    extern __shared__ float4 wq4[];   // [9][QUADS_PER_CTA] weight quads
    const int cta  = blockIdx.x;
    const int tid  = threadIdx.x;
    const int lq   = tid;                         // this thread's quad
    const int g0   = (cta * QUADS_PER_CTA + lq) * 4;   // global pixel base
    const int b    = cta / CTAS_PER_BATCH;        // batch of this CTA

    if (cta == 0 && tid < KB) g_cnt[tid] = 0;     // pre-barrier; atomics are post

    const float* f0 = fm + (size_t)(b * 3 + 0) * KHW;
    const float* f1 = fm + (size_t)(b * 3 + 1) * KHW;
    const float* f2 = fm + (size_t)(b * 3 + 2) * KHW;

    // ================= phase 1: weights -> smem, init state -> g_mA ========
    // Weight (bit-faithful to reference): w = 3*exp(-2*sum_c d_c^2 - SP_k),
    // zero padding applied AFTER fm+10 -> OOB gives exp(~-600) == +0.0f
    // exactly, which licenses the branch-free iteration below.
    // Init: xm = x*t > 0.5 -> ch1=0.55 else 0.45, ch0 = 1-ch1 (exact in fp32).
    {
        const float sp1 = 1.0f / 1800.0f;
        const float sp2 = 2.0f / 1800.0f;
        const float SP[9] = { sp2, sp1, sp2,  sp1, 0.f, sp1,  sp2, sp1, sp2 };

        int p  = g0 - b * KHW;            // batch-local pixel
        int y  = p / KW, xc = p - y * KW;

        // ---- init mask word ----
        float4 xv = *(const float4*)(x + g0);
        float4 tv = *(const float4*)(tgt + g0);
        float xs[4] = { xv.x, xv.y, xv.z, xv.w };
        float ts[4] = { tv.x, tv.y, tv.z, tv.w };
        uint32_t mw = 0;
#pragma unroll
        for (int j = 0; j < 4; j++) {
            unsigned m1 = (__fmul_rn(xs[j], ts[j]) > 0.5f) ? 1u : 0u;
            mw |= (m1 | ((m1 ^ 1u) << 1)) << (8 * j);
        }
        *(uint32_t*)(g_mA_raw + MPAD + g0) = mw;

        // ---- center values for the 4 pixels ----
        float c0[4], c1[4], c2[4];
#pragma unroll
        for (int j = 0; j < 4; j++) {
            c0[j] = __fadd_rn(f0[p + j], 10.0f);
            c1[j] = __fadd_rn(f1[p + j], 10.0f);
            c2[j] = __fadd_rn(f2[p + j], 10.0f);
        }

        // ---- 9 weights x 4 pixels ----
#pragma unroll
        for (int k = 0; k < 9; k++) {
            int ny = y + k / 3 - 1;
            int kx = k % 3 - 1;
            float wv[4];
#pragma unroll
            for (int j = 0; j < 4; j++) {
                int nx = xc + j + kx;
                float n0 = 0.0f, n1 = 0.0f, n2 = 0.0f;  // pad AFTER +10
                if (ny >= 0 && ny < KH && nx >= 0 && nx < KW) {
                    int q = ny * KW + nx;
                    n0 = __fadd_rn(f0[q], 10.0f);
                    n1 = __fadd_rn(f1[q], 10.0f);
                    n2 = __fadd_rn(f2[q], 10.0f);
                }
                float d0 = __fsub_rn(n0, c0[j]);
                float d1 = __fsub_rn(n1, c1[j]);
                float d2 = __fsub_rn(n2, c2[j]);
                float ss = __fadd_rn(__fadd_rn(__fmul_rn(d0, d0),
                                               __fmul_rn(d1, d1)),
                                     __fmul_rn(d2, d2));
                float color = __fmul_rn(ss, -2.0f);   // exact: -ss/0.5
                float arg   = __fsub_rn(color, SP[k]);
                wv[j] = __fmul_rn(3.0f, expf(arg));
            }
            wq4[k * QUADS_PER_CTA + lq] =
                make_float4(wv[0], wv[1], wv[2], wv[3]);
        }
    }
    grid_barrier();   // init masks + (local) weights ready

    // ================= phase 2: 20 mean-field iterations ===================
    // Per pixel (bit-faithful): a{0,1} = sum_k w_k * (-log r_k) in k order
    // (separate rn mul/add); f0=exp(-a0); f1=exp(-a1)*t; +1e-6; two IEEE
    // divisions; two independent >0.5 thresholds. OOB neighbors: w == +0.0f
    // exactly, u is finite -> contribution +0.0f regardless of pad bytes.
    const float L45 = -logf(0.45f);
    const float L55 = -logf(0.55f);

    float4 tv = *(const float4*)(tgt + g0);
    const float ts[4] = { tv.x, tv.y, tv.z, tv.w };

#pragma unroll 1
    for (int it = 0; it < ITERS; it++) {
        const unsigned char* __restrict__ mIn  =
            ((it & 1) ? g_mB_raw : g_mA_raw) + MPAD;
        unsigned char* __restrict__ mOut =
            ((it & 1) ? g_mA_raw : g_mB_raw) + MPAD;

        // front-batched gmem loads: 9 mask words
        uint32_t Wm[3][3];
#pragma unroll
        for (int r = 0; r < 3; r++) {
            const unsigned char* row = mIn + g0 + (r - 1) * KW;
            Wm[r][0] = *(const uint32_t*)(row - 4);
            Wm[r][1] = *(const uint32_t*)(row);
            Wm[r][2] = *(const uint32_t*)(row + 4);
        }

        // weights from smem
        float4 wk[9];
#pragma unroll
        for (int k = 0; k < 9; k++)
            wk[k] = wq4[k * QUADS_PER_CTA + lq];

        // u windows (each slot shared by up to 3 of the 4 pixels)
        float u0v[3][6], u1v[3][6];
#pragma unroll
        for (int r = 0; r < 3; r++) {
#pragma unroll
            for (int t = -1; t <= 4; t++) {
                unsigned m = byte_at(Wm[r], t);
                u0v[r][t + 1] = (m & 2u) ? L55 : L45;
                u1v[r][t + 1] = (m & 1u) ? L55 : L45;
            }
        }

        float a0[4] = {0.f, 0.f, 0.f, 0.f};
        float a1[4] = {0.f, 0.f, 0.f, 0.f};
#pragma unroll
        for (int r = 0; r < 3; r++) {
#pragma unroll
            for (int c = 0; c < 3; c++) {
                int k = r * 3 + c;
                float ws[4] = { wk[k].x, wk[k].y, wk[k].z, wk[k].w };
#pragma unroll
                for (int j = 0; j < 4; j++) {
                    a0[j] = __fadd_rn(a0[j], __fmul_rn(ws[j], u0v[r][j + c]));
                    a1[j] = __fadd_rn(a1[j], __fmul_rn(ws[j], u1v[r][j + c]));
                }
            }
        }

        uint32_t outw = 0;
#pragma unroll
        for (int j = 0; j < 4; j++) {
            float f0e = expf(-a0[j]);
            float f1e = __fmul_rn(expf(-a1[j]), ts[j]);
            f0e = __fadd_rn(f0e, 1e-6f);
            f1e = __fadd_rn(f1e, 1e-6f);
            float s = __fadd_rn(f0e, f1e);
            unsigned nm = 0;
            if (__fdiv_rn(f1e, s) > 0.5f) nm |= 1u;
            if (__fdiv_rn(f0e, s) > 0.5f) nm |= 2u;
            outw |= nm << (8 * j);
        }
        *(uint32_t*)(mOut + g0) = outw;

        grid_barrier();   // also publishes mOut for neighbor CTAs
    }
    // ITERS even -> final state in g_mA

    // ================= phase 3: output + validity ==========================
    uint32_t w = *(const uint32_t*)(g_mA_raw + MPAD + g0);
    float4 ov;
    ov.x = (float)( w        & 1u);
    ov.y = (float)((w >> 8)  & 1u);
    ov.z = (float)((w >> 16) & 1u);
    ov.w = (float)((w >> 24) & 1u);
    *(float4*)(out + g0) = ov;

    int cnt = __popc(w & 0x01010101u);
#pragma unroll
    for (int d = 16; d > 0; d >>= 1)
        cnt += __shfl_down_sync(0xffffffffu, cnt, d);
    if ((tid & 31) == 0) atomicAdd(&g_cnt[b], cnt);

    grid_barrier();       // all counts in

    // valid = (count >= HW*0.05=7372.8) && (count <= HW*0.95=140083.2);
    // count is an exact integer -> >=7373 && <=140083.
    if (cta == 0 && tid < KB) {
        int c = g_cnt[tid];
        out[NPIX + tid] = (c >= 7373 && c <= 140083) ? 1.0f : 0.0f;
    }
}

extern "C" void kernel_launch(void* const* d_in, const int* in_sizes, int n_in,
                              void* d_out, int out_size) {
    (void)in_sizes; (void)n_in; (void)out_size;
    const float* x   = (const float*)d_in[0];   // [4,1,384,384]
    const float* tgt = (const float*)d_in[1];   // [4,1,384,384]
    const float* fm  = (const float*)d_in[2];   // [4,3,384,384]
    float* out = (float*)d_out;                 // [4*384*384 mask] ++ [4 valid]

    // 147456 B dynamic smem > 48 KB default: opt in every call (idempotent,
    // not a stream op -> graph-capture safe).
    cudaFuncSetAttribute(mf_persistent_kernel,
                         cudaFuncAttributeMaxDynamicSharedMemorySize,
                         SMEM_BYTES);
    mf_persistent_kernel<<<NCTA, NTH, SMEM_BYTES>>>(x, tgt, fm, out);
}

// round 11
// speedup vs baseline: 1.4691x; 1.2221x over previous
#include <cuda_runtime.h>
#include <stdint.h>

// MeanField on GB300 — persistent kernel, log-domain decision version.
// 144 CTAs x 1024 threads (1 CTA/SM by smem; all co-resident -> grid barrier
// safe). Thread t of CTA c owns the 4-pixel quad c*1024+t.
//
// Key algebra: state is binary (each channel 0.45/0.55), so with
// D = ln(0.55/0.45), c_k = +1 (ch1 high) / -1 (ch0 high) / 0 (tie):
//   f1/s > 0.5  <=>  exp(-a1)*t > exp(-a0)  <=>  sum_k w_k c_k > -ln(t)/D = T
//   f0/s > 0.5  <=>  sum_k w_k c_k < T
// (tie -> both false -> c=0 next iter; t=0 -> T=+inf -> ch0 high; both match
// the reference). Decisions are exact in infinite precision; fp deviation
// ~1e-6 on a decision variable whose margins were shown (rel_err=0.0 twice
// vs the CPU reference with ~1e-7 transcendental noise) to be far larger.

#define KW   384
#define KH   384
#define KHW  (KW * KH)              // 147456
#define KB   4
#define NPIX (KB * KHW)             // 589824
#define ITERS 20

#define NCTA 144
#define NTH  1024
#define QUADS_PER_CTA 1024
#define CTAS_PER_BATCH 36
#define SMEM_BYTES (9 * QUADS_PER_CTA * 16)   // 147456 B

#define MPAD 512                    // mask pad (never written -> stays 0)

static __device__ __align__(16) unsigned char g_mA_raw[NPIX + 2 * MPAD];
static __device__ __align__(16) unsigned char g_mB_raw[NPIX + 2 * MPAD];
static __device__ int g_cnt[KB];
static __device__ int g_bar_count;  // drains to 0 each episode
static __device__ int g_bar_gen;    // monotone across graph replays

__device__ __forceinline__ void grid_barrier() {
    __syncthreads();
    if (threadIdx.x == 0) {
        int gen = *(volatile int*)&g_bar_gen;
        __threadfence();
        if (atomicAdd(&g_bar_count, 1) == NCTA - 1) {
            atomicExch(&g_bar_count, 0);
            __threadfence();
            atomicAdd(&g_bar_gen, 1);
        } else {
            while (*(volatile int*)&g_bar_gen == gen) { }
            __threadfence();
        }
    }
    __syncthreads();
}

// signed byte at window slot s (s in 0..5 -> byte offset s-1 from quad base)
__device__ __forceinline__ int sbyte_at(const uint32_t W[3], int s) {
    int t = s - 1;
    if (t < 0)  return (int)W[0] >> 24;                     // byte -1
    if (t < 4)  return ((int)(W[1] << (24 - 8 * t))) >> 24; // bytes 0..3
    return ((int)(W[2] << 24)) >> 24;                       // byte 4
}

__global__ void __launch_bounds__(NTH, 1) mf_persistent_kernel(
    const float* __restrict__ x,
    const float* __restrict__ tgt,
    const float* __restrict__ fm,
    float* __restrict__ out)
{
    extern __shared__ float4 wq4[];   // [9][QUADS_PER_CTA] weight quads
    const int cta = blockIdx.x;
    const int tid = threadIdx.x;
    const int lq  = tid;
    const int g0  = (cta * QUADS_PER_CTA + lq) * 4;
    const int b   = cta / CTAS_PER_BATCH;

    if (cta == 0 && tid < KB) g_cnt[tid] = 0;

    const float* f0 = fm + (size_t)(b * 3 + 0) * KHW;
    const float* f1 = fm + (size_t)(b * 3 + 1) * KHW;
    const float* f2 = fm + (size_t)(b * 3 + 2) * KHW;

    // ======== phase 1: weights -> smem, init mask, per-pixel threshold ======
    // w = 3*exp(-2*sum_c d_c^2 - SP_k); zero pad AFTER fm+10 -> OOB w == +0.0f
    // exactly (licenses branch-free FFMA accumulation: 0 * finite == 0).
    float T[4];
    {
        // D = ln(0.55/0.45) via the compile-time-folded logf constants
        const float L45 = -logf(0.45f);
        const float L55 = -logf(0.55f);
        const float invD = 1.0f / (L45 - L55);

        float4 xv = *(const float4*)(x + g0);
        float4 tv = *(const float4*)(tgt + g0);
        float xs[4] = { xv.x, xv.y, xv.z, xv.w };
        float ts[4] = { tv.x, tv.y, tv.z, tv.w };

        // per-pixel decision threshold (t=0 -> +inf -> always ch0-high: correct)
#pragma unroll
        for (int j = 0; j < 4; j++)
            T[j] = __fmul_rn(-logf(ts[j]), invD);

        uint32_t mw = 0;
#pragma unroll
        for (int j = 0; j < 4; j++) {
            unsigned m1 = (__fmul_rn(xs[j], ts[j]) > 0.5f) ? 1u : 0u;
            mw |= (m1 ? 0x01u : 0xFFu) << (8 * j);
        }
        *(uint32_t*)(g_mA_raw + MPAD + g0) = mw;

        const float sp1 = 1.0f / 1800.0f;
        const float sp2 = 2.0f / 1800.0f;
        const float SP[9] = { sp2, sp1, sp2,  sp1, 0.f, sp1,  sp2, sp1, sp2 };

        int p = g0 - b * KHW;
        int y = p / KW, xc = p - y * KW;

        float c0[4], c1[4], c2[4];
#pragma unroll
        for (int j = 0; j < 4; j++) {
            c0[j] = __fadd_rn(f0[p + j], 10.0f);
            c1[j] = __fadd_rn(f1[p + j], 10.0f);
            c2[j] = __fadd_rn(f2[p + j], 10.0f);
        }

#pragma unroll
        for (int k = 0; k < 9; k++) {
            int ny = y + k / 3 - 1;
            int kx = k % 3 - 1;
            float wv[4];
#pragma unroll
            for (int j = 0; j < 4; j++) {
                int nx = xc + j + kx;
                float n0 = 0.0f, n1 = 0.0f, n2 = 0.0f;
                if (ny >= 0 && ny < KH && nx >= 0 && nx < KW) {
                    int q = ny * KW + nx;
                    n0 = __fadd_rn(f0[q], 10.0f);
                    n1 = __fadd_rn(f1[q], 10.0f);
                    n2 = __fadd_rn(f2[q], 10.0f);
                }
                float d0 = __fsub_rn(n0, c0[j]);
                float d1 = __fsub_rn(n1, c1[j]);
                float d2 = __fsub_rn(n2, c2[j]);
                float ss = __fadd_rn(__fadd_rn(__fmul_rn(d0, d0),
                                               __fmul_rn(d1, d1)),
                                     __fmul_rn(d2, d2));
                float arg = __fsub_rn(__fmul_rn(ss, -2.0f), SP[k]);
                wv[j] = __fmul_rn(3.0f, expf(arg));
            }
            wq4[k * QUADS_PER_CTA + lq] = make_float4(wv[0], wv[1], wv[2], wv[3]);
        }
    }
    grid_barrier();   // masks + weights published

    // ======== phase 2: 20 iterations, log-domain decisions =================
    // Mask byte encoding: +1 = ch1 high, 0xFF (-1) = ch0 high, 0 = tie.
    // acc_j = sum_k w_kj * c_k;  decisions: >T -> 0x01, <T -> 0xFF, else 0.
#pragma unroll 1
    for (int it = 0; it < ITERS; it++) {
        const unsigned char* __restrict__ mIn  =
            ((it & 1) ? g_mB_raw : g_mA_raw) + MPAD;
        unsigned char* __restrict__ mOut =
            ((it & 1) ? g_mA_raw : g_mB_raw) + MPAD;

        // front-batched: 9 mask words
        uint32_t Wm[3][3];
#pragma unroll
        for (int r = 0; r < 3; r++) {
            const unsigned char* row = mIn + g0 + (r - 1) * KW;
            Wm[r][0] = *(const uint32_t*)(row - 4);
            Wm[r][1] = *(const uint32_t*)(row);
            Wm[r][2] = *(const uint32_t*)(row + 4);
        }

        float4 wk[9];
#pragma unroll
        for (int k = 0; k < 9; k++)
            wk[k] = wq4[k * QUADS_PER_CTA + lq];

        // window c values as floats (slot s <-> byte g0+s-1)
        float cf[3][6];
#pragma unroll
        for (int r = 0; r < 3; r++)
#pragma unroll
            for (int s = 0; s < 6; s++)
                cf[r][s] = (float)sbyte_at(Wm[r], s);

        float acc[4] = {0.f, 0.f, 0.f, 0.f};
#pragma unroll
        for (int r = 0; r < 3; r++) {
#pragma unroll
            for (int c = 0; c < 3; c++) {
                int k = r * 3 + c;
                float ws[4] = { wk[k].x, wk[k].y, wk[k].z, wk[k].w };
#pragma unroll
                for (int j = 0; j < 4; j++)
                    acc[j] = fmaf(ws[j], cf[r][j + c], acc[j]);
            }
        }

        uint32_t outw = 0;
#pragma unroll
        for (int j = 0; j < 4; j++) {
            unsigned nm = (acc[j] > T[j]) ? 0x01u
                        : ((acc[j] < T[j]) ? 0xFFu : 0x00u);
            outw |= nm << (8 * j);
        }
        *(uint32_t*)(mOut + g0) = outw;

        grid_barrier();
    }
    // ITERS even -> final state in g_mA

    // ======== phase 3: output + validity ===================================
    uint32_t w = *(const uint32_t*)(g_mA_raw + MPAD + g0);
    // per-byte: on = (byte == 0x01) = bit0 & ~bit1
    uint32_t on = w & ~(w >> 1) & 0x01010101u;
    float4 ov;
    ov.x = (float)( on        & 1u);
    ov.y = (float)((on >> 8)  & 1u);
    ov.z = (float)((on >> 16) & 1u);
    ov.w = (float)((on >> 24) & 1u);
    *(float4*)(out + g0) = ov;

    int cnt = __popc(on);
#pragma unroll
    for (int d = 16; d > 0; d >>= 1)
        cnt += __shfl_down_sync(0xffffffffu, cnt, d);
    if ((tid & 31) == 0) atomicAdd(&g_cnt[b], cnt);

    grid_barrier();

    // valid: count integer in [7373, 140083]  (HW*0.05=7372.8, HW*0.95=140083.2)
    if (cta == 0 && tid < KB) {
        int c = g_cnt[tid];
        out[NPIX + tid] = (c >= 7373 && c <= 140083) ? 1.0f : 0.0f;
    }
}

extern "C" void kernel_launch(void* const* d_in, const int* in_sizes, int n_in,
                              void* d_out, int out_size) {
    (void)in_sizes; (void)n_in; (void)out_size;
    const float* x   = (const float*)d_in[0];
    const float* tgt = (const float*)d_in[1];
    const float* fm  = (const float*)d_in[2];
    float* out = (float*)d_out;

    cudaFuncSetAttribute(mf_persistent_kernel,
                         cudaFuncAttributeMaxDynamicSharedMemorySize,
                         SMEM_BYTES);
    mf_persistent_kernel<<<NCTA, NTH, SMEM_BYTES>>>(x, tgt, fm, out);
}